// round 10
// baseline (speedup 1.0000x reference)
#include <cuda_runtime.h>
#include <cuda_bf16.h>
#include <cstdint>

static constexpr int N_EMBD = 1024;
static constexpr int D_FF   = 4096;
static constexpr int MAX_M  = 8192;
static constexpr int R      = 16;
static constexpr int NB2    = D_FF / 128;   // GEMM1 n-blocks = t2 partial slices (32)

// ---------------- scratch (device globals; no allocations allowed) ----------
__device__ signed char g_xq[(size_t)MAX_M * N_EMBD];
__device__ signed char g_wq_fc[(size_t)D_FF * N_EMBD];
__device__ signed char g_wq_proj[(size_t)N_EMBD * D_FF];
__device__ float       g_h[(size_t)MAX_M * D_FF];
__device__ signed char g_hq[(size_t)MAX_M * D_FF];
__device__ float       g_t1[(size_t)MAX_M * R];
__device__ float       g_t2[(size_t)MAX_M * R];
__device__ float       g_tpart[(size_t)NB2 * MAX_M * R];
__device__ int         g_maxbits[4];        // |x|,|W_fc|,|W_proj|,|h|

__device__ __forceinline__ void cp_async16(void* d, const void* s) {
    unsigned u = (unsigned)__cvta_generic_to_shared(d);
    asm volatile("cp.async.cg.shared.global [%0], [%1], 16;\n" :: "r"(u), "l"(s));
}
__device__ __forceinline__ void cp_commit() {
    asm volatile("cp.async.commit_group;\n" ::: "memory");
}
__device__ __forceinline__ uint32_t smem_u32(const void* p) {
    return (uint32_t)__cvta_generic_to_shared(p);
}
__device__ __forceinline__ void ldsm4(uint32_t* r, uint32_t addr) {
    asm volatile("ldmatrix.sync.aligned.m8n8.x4.shared.b16 {%0,%1,%2,%3}, [%4];"
        : "=r"(r[0]), "=r"(r[1]), "=r"(r[2]), "=r"(r[3]) : "r"(addr));
}
__device__ __forceinline__ void imma(int* d, const uint32_t* a, const uint32_t* b) {
    asm volatile("mma.sync.aligned.m16n8k32.row.col.s32.s8.s8.s32 "
        "{%0,%1,%2,%3}, {%4,%5,%6,%7}, {%8,%9}, {%0,%1,%2,%3};"
        : "+r"(d[0]), "+r"(d[1]), "+r"(d[2]), "+r"(d[3])
        : "r"(a[0]), "r"(a[1]), "r"(a[2]), "r"(a[3]), "r"(b[0]), "r"(b[1]));
}

// ---------------------------------------------------------------------------
__global__ void init_kernel(int* mb) { if (threadIdx.x < 4) mb[threadIdx.x] = 0; }

__global__ void absmax_kernel(const float4* __restrict__ x, int n4, int* __restrict__ out) {
    float m = 0.f;
    for (int i = blockIdx.x * blockDim.x + threadIdx.x; i < n4; i += gridDim.x * blockDim.x) {
        float4 v = x[i];
        m = fmaxf(m, fmaxf(fmaxf(fabsf(v.x), fabsf(v.y)), fmaxf(fabsf(v.z), fabsf(v.w))));
    }
    #pragma unroll
    for (int o = 16; o; o >>= 1) m = fmaxf(m, __shfl_down_sync(0xffffffffu, m, o));
    __shared__ float sm[8];
    if ((threadIdx.x & 31) == 0) sm[threadIdx.x >> 5] = m;
    __syncthreads();
    if (threadIdx.x == 0) {
        float mm = sm[0];
        #pragma unroll
        for (int w = 1; w < 8; w++) mm = fmaxf(mm, sm[w]);
        atomicMax(out, __float_as_int(mm));
    }
}

// ---------------------------------------------------------------------------
// t1 = X @ A^T fused abs-max. BM=64, 256 threads (proven R6 shape @32us)
// ---------------------------------------------------------------------------
__global__ void __launch_bounds__(256) rowdot_x_kernel(
    const float* __restrict__ X, const float* __restrict__ A, int K,
    float* __restrict__ T, int* __restrict__ maxout)
{
    constexpr int LDS = 36;
    constexpr int STG = (64 + 16) * LDS;
    __shared__ __align__(16) float sm[3 * STG];
    __shared__ float mred[8];
    const int tid = threadIdx.x;
    const int m0  = blockIdx.x * 64;
    const int rg  = tid >> 3, cg = tid & 7;
    const float* Xg = X + (size_t)m0 * K;

    auto issue = [&](int kt) {
        float* Xs = sm + (kt % 3) * STG;
        float* As = Xs + 64 * LDS;
        #pragma unroll
        for (int l = 0; l < 2; l++) {
            int i = tid + l * 256, r = i >> 3, c = i & 7;
            cp_async16(Xs + r * LDS + c * 4, Xg + (size_t)r * K + kt * 32 + c * 4);
        }
        if (tid < 128) {
            int r = tid >> 3, c = tid & 7;
            cp_async16(As + r * LDS + c * 4, A + (size_t)r * K + kt * 32 + c * 4);
        }
        cp_commit();
    };

    const int KT = K / 32;
    issue(0); issue(1);
    float acc[2][2] = {};
    float mx = 0.f;

    for (int kt = 0; kt < KT; kt++) {
        asm volatile("cp.async.wait_group 1;\n" ::: "memory");
        __syncthreads();
        if (kt + 2 < KT) issue(kt + 2); else cp_commit();
        const float* Xs = sm + (kt % 3) * STG;
        const float* As = Xs + 64 * LDS;
        #pragma unroll
        for (int kq = 0; kq < 8; kq++) {
            float4 xv0 = *(const float4*)(Xs + (rg * 2)     * LDS + kq * 4);
            float4 xv1 = *(const float4*)(Xs + (rg * 2 + 1) * LDS + kq * 4);
            float4 av0 = *(const float4*)(As + (cg * 2)     * LDS + kq * 4);
            float4 av1 = *(const float4*)(As + (cg * 2 + 1) * LDS + kq * 4);
            mx = fmaxf(mx, fmaxf(fmaxf(fabsf(xv0.x), fabsf(xv0.y)), fmaxf(fabsf(xv0.z), fabsf(xv0.w))));
            mx = fmaxf(mx, fmaxf(fmaxf(fabsf(xv1.x), fabsf(xv1.y)), fmaxf(fabsf(xv1.z), fabsf(xv1.w))));
            acc[0][0] += xv0.x*av0.x + xv0.y*av0.y + xv0.z*av0.z + xv0.w*av0.w;
            acc[0][1] += xv0.x*av1.x + xv0.y*av1.y + xv0.z*av1.z + xv0.w*av1.w;
            acc[1][0] += xv1.x*av0.x + xv1.y*av0.y + xv1.z*av0.z + xv1.w*av0.w;
            acc[1][1] += xv1.x*av1.x + xv1.y*av1.y + xv1.z*av1.z + xv1.w*av1.w;
        }
        __syncthreads();
    }
    #pragma unroll
    for (int ii = 0; ii < 2; ii++)
        #pragma unroll
        for (int jj = 0; jj < 2; jj++)
            T[(size_t)(m0 + rg * 2 + ii) * R + cg * 2 + jj] = acc[ii][jj];

    #pragma unroll
    for (int o = 16; o; o >>= 1) mx = fmaxf(mx, __shfl_down_sync(0xffffffffu, mx, o));
    if ((tid & 31) == 0) mred[tid >> 5] = mx;
    __syncthreads();
    if (tid == 0) {
        float m = mred[0];
        #pragma unroll
        for (int i = 1; i < 8; i++) m = fmaxf(m, mred[i]);
        atomicMax(maxout, __float_as_int(m));
    }
}

// q = clip(round(v/scale),-127,127) stored as int8.
__global__ void quant_kernel(const float4* __restrict__ src, int n4,
                             const int* __restrict__ mb, char4* __restrict__ dst) {
    const float s = fmaxf(__int_as_float(*mb), 1e-8f) / 127.0f;
    for (int i = blockIdx.x * blockDim.x + threadIdx.x; i < n4; i += gridDim.x * blockDim.x) {
        float4 v = src[i];
        char4 q;
        q.x = (signed char)(int)fminf(fmaxf(rintf(v.x / s), -127.f), 127.f);
        q.y = (signed char)(int)fminf(fmaxf(rintf(v.y / s), -127.f), 127.f);
        q.z = (signed char)(int)fminf(fmaxf(rintf(v.z / s), -127.f), 127.f);
        q.w = (signed char)(int)fminf(fmaxf(rintf(v.w / s), -127.f), 127.f);
        dst[i] = q;
    }
}

__global__ void reduce_t2_kernel(const float* __restrict__ Tpart, float* __restrict__ T2,
                                 int n, int nb) {
    int i = blockIdx.x * blockDim.x + threadIdx.x;
    if (i < n) {
        float s = 0.f;
        for (int b = 0; b < nb; b++) s += Tpart[(size_t)b * n + i];
        T2[i] = s;
    }
}

// ---------------------------------------------------------------------------
// int8 GEMM: C = s*(Aq@Bq^T) + bias + 2*(T@Blora^T)  [+GELU]
// BM=128 BN=128 BK=64. 4 warps (2m x 2n), warp tile 64x64 -> 4 IMMA per LDSM.
// 5-stage cp.async, 4 tiles in flight, prefetch issued BEFORE compute
// (stage (kt+4)%5 == (kt-1)%5 is protected by the top-of-iter syncthreads).
// ---------------------------------------------------------------------------
template <bool GELU, bool FUSE_T2>
__global__ void __launch_bounds__(128, 2) gemm_kernel(
    const signed char* __restrict__ Aq, const signed char* __restrict__ Bq,
    const float* __restrict__ bias, const float* __restrict__ T,
    const float* __restrict__ Blora, const int* __restrict__ mbA,
    const int* __restrict__ mbW, float* __restrict__ C,
    const float* __restrict__ Ap, float* __restrict__ Tpart, int* __restrict__ hmax,
    int M, int N, int K)
{
    constexpr int BM = 128, BN = 128, BK = 64, LDA = 80;
    constexpr int STAGE = 2 * BM * LDA;           // A(10240) + B(10240) bytes
    extern __shared__ __align__(16) char smem[];  // 5*20480 = 102400
    __shared__ float hred[4];

    const int tid = threadIdx.x;
    const int lane = tid & 31;
    const int m0 = blockIdx.y * BM, n0 = blockIdx.x * BN;
    const int w = tid >> 5, wm = w & 1, wn = w >> 1;

    const signed char* Agb = Aq + (size_t)m0 * K;
    const signed char* Bgb = Bq + (size_t)n0 * K;

    auto issue = [&](int kt) {
        char* as = smem + (kt % 5) * STAGE;
        char* bs = as + BM * LDA;
        const signed char* ag = Agb + kt * BK;
        const signed char* bg = Bgb + kt * BK;
        #pragma unroll
        for (int l = 0; l < 4; l++) {
            int i = tid + l * 128, r = i >> 2, c = i & 3;
            cp_async16(as + r * LDA + c * 16, ag + (size_t)r * K + c * 16);
        }
        #pragma unroll
        for (int l = 0; l < 4; l++) {
            int i = tid + l * 128, r = i >> 2, c = i & 3;
            cp_async16(bs + r * LDA + c * 16, bg + (size_t)r * K + c * 16);
        }
        cp_commit();
    };

    // ldmatrix lane addressing
    const uint32_t a_off = (uint32_t)((wm * 64 + (lane & 15)) * LDA + ((lane >> 4) << 4));
    const int brow = (lane & 7) + ((lane & 16) >> 1);
    const uint32_t b_off = (uint32_t)((wn * 64 + brow) * LDA + (((lane >> 3) & 1) << 4));

    const int KT = K / BK;
    issue(0); issue(1); issue(2); issue(3);

    int d[4][8][4];                               // [m16][n8][frag]
    #pragma unroll
    for (int i = 0; i < 4; i++)
        #pragma unroll
        for (int j = 0; j < 8; j++)
            #pragma unroll
            for (int q = 0; q < 4; q++) d[i][j][q] = 0;

    for (int kt = 0; kt < KT; kt++) {
        asm volatile("cp.async.wait_group 3;\n" ::: "memory");
        __syncthreads();
        if (kt + 4 < KT) issue(kt + 4); else cp_commit();

        uint32_t a_s = smem_u32(smem + (kt % 5) * STAGE);
        uint32_t b_s = a_s + BM * LDA;
        #pragma unroll
        for (int ks = 0; ks < 2; ks++) {
            uint32_t af[4][4], bf[8][2];
            #pragma unroll
            for (int i = 0; i < 4; i++)
                ldsm4(af[i], a_s + a_off + i * (16 * LDA) + ks * 32);
            #pragma unroll
            for (int g = 0; g < 4; g++) {
                uint32_t t[4];
                ldsm4(t, b_s + b_off + g * (16 * LDA) + ks * 32);
                bf[2*g][0] = t[0]; bf[2*g][1] = t[1];
                bf[2*g+1][0] = t[2]; bf[2*g+1][1] = t[3];
            }
            #pragma unroll
            for (int i = 0; i < 4; i++)
                #pragma unroll
                for (int j = 0; j < 8; j++)
                    imma(d[i][j], af[i], bf[j]);
        }
    }
    asm volatile("cp.async.wait_group 0;\n" ::: "memory");
    __syncthreads();

    // ---------------- epilogue (aliases pipeline smem) ----------------
    const float sA = fmaxf(__int_as_float(*mbA), 1e-8f) / 127.0f;
    const float sW = fmaxf(__int_as_float(*mbW), 1e-8f) / 127.0f;
    const float sc = sA * sW;

    int*   parkI = (int*)smem;                    // [128][68]  = 34816 B
    float* parkF = (float*)smem;
    float* Tsm   = (float*)(smem + 34816);        // [128][16]  =  8192 B
    float* Bl    = (float*)(smem + 43008);        // [128][16]  =  8192 B
    float* Apsm  = (float*)(smem + 51200);        // [16][132]  =  8448 B

    #pragma unroll
    for (int l = 0; l < 4; l++) {
        ((float4*)Bl)[tid + l * 128]  = ((const float4*)(Blora + (size_t)n0 * R))[tid + l * 128];
        ((float4*)Tsm)[tid + l * 128] = ((const float4*)(T + (size_t)m0 * R))[tid + l * 128];
    }
    if (FUSE_T2)
        for (int i = tid; i < R * BN; i += 128) {
            int j = i >> 7, c = i & 127;
            Apsm[j * 132 + c] = Ap[(size_t)j * N + n0 + c];
        }

    float hm = 0.f;
    float acc2[16] = {};
    const int jj = tid & 15, rgp = tid >> 4;      // 16 j x 8 row-groups(16 rows)
    const int ec = tid & 63, er0 = tid >> 6;      // column-per-thread map (2 rows start)

    #pragma unroll
    for (int half = 0; half < 2; half++) {
        __syncthreads();
        if (wn == half) {                         // 2 warps park 128 rows x 64 cols
            #pragma unroll
            for (int i = 0; i < 4; i++) {
                int r0 = wm * 64 + i * 16 + (lane >> 2);
                #pragma unroll
                for (int j = 0; j < 8; j++) {
                    int c = j * 8 + (lane & 3) * 2;
                    parkI[r0 * 68 + c]           = d[i][j][0];
                    parkI[r0 * 68 + c + 1]       = d[i][j][1];
                    parkI[(r0 + 8) * 68 + c]     = d[i][j][2];
                    parkI[(r0 + 8) * 68 + c + 1] = d[i][j][3];
                }
            }
        }
        __syncthreads();

        const int gc = half * 64 + ec;
        const float bsv = __ldg(bias + n0 + gc);
        float4 bl0 = *(float4*)(Bl + gc * 16);
        float4 bl1 = *(float4*)(Bl + gc * 16 + 4);
        float4 bl2 = *(float4*)(Bl + gc * 16 + 8);
        float4 bl3 = *(float4*)(Bl + gc * 16 + 12);

        for (int r = er0; r < BM; r += 2) {
            float4 t0 = *(float4*)(Tsm + r * 16);
            float4 t1 = *(float4*)(Tsm + r * 16 + 4);
            float4 t2v = *(float4*)(Tsm + r * 16 + 8);
            float4 t3 = *(float4*)(Tsm + r * 16 + 12);
            float lor = t0.x*bl0.x + t0.y*bl0.y + t0.z*bl0.z + t0.w*bl0.w
                      + t1.x*bl1.x + t1.y*bl1.y + t1.z*bl1.z + t1.w*bl1.w
                      + t2v.x*bl2.x + t2v.y*bl2.y + t2v.z*bl2.z + t2v.w*bl2.w
                      + t3.x*bl3.x + t3.y*bl3.y + t3.z*bl3.z + t3.w*bl3.w;
            float v = sc * (float)parkI[r * 68 + ec] + bsv + 2.0f * lor;
            if (GELU) v = 0.5f * v * (1.0f + erff(v * 0.7071067811865476f));
            C[(size_t)(m0 + r) * N + n0 + gc] = v;
            if (FUSE_T2) { parkF[r * 68 + ec] = v; hm = fmaxf(hm, fabsf(v)); }
        }
        if (FUSE_T2) {
            __syncthreads();
            #pragma unroll
            for (int cq = 0; cq < 16; cq++) {
                float4 av = *(float4*)(Apsm + jj * 132 + half * 64 + cq * 4);
                #pragma unroll
                for (int ii = 0; ii < 16; ii++) {
                    float4 hv = *(float4*)(parkF + (rgp * 16 + ii) * 68 + cq * 4);
                    acc2[ii] += hv.x * av.x + hv.y * av.y + hv.z * av.z + hv.w * av.w;
                }
            }
        }
    }
    if (FUSE_T2) {
        #pragma unroll
        for (int ii = 0; ii < 16; ii++)
            Tpart[(size_t)blockIdx.x * ((size_t)M * R)
                  + (size_t)(m0 + rgp * 16 + ii) * R + jj] = acc2[ii];
        #pragma unroll
        for (int o = 16; o; o >>= 1) hm = fmaxf(hm, __shfl_down_sync(0xffffffffu, hm, o));
        if ((tid & 31) == 0) hred[w] = hm;
        __syncthreads();
        if (tid == 0) {
            float m = fmaxf(fmaxf(hred[0], hred[1]), fmaxf(hred[2], hred[3]));
            atomicMax(hmax, __float_as_int(m));
        }
    }
}

// ---------------------------------------------------------------------------
extern "C" void kernel_launch(void* const* d_in, const int* in_sizes, int n_in,
                              void* d_out, int out_size) {
    const float* x      = (const float*)d_in[0];
    const float* W_fc   = (const float*)d_in[1];
    const float* b_fc   = (const float*)d_in[2];
    const float* A_fc   = (const float*)d_in[3];
    const float* B_fc   = (const float*)d_in[4];
    const float* W_proj = (const float*)d_in[5];
    const float* b_proj = (const float*)d_in[6];
    const float* A_proj = (const float*)d_in[7];
    const float* B_proj = (const float*)d_in[8];
    float* out = (float*)d_out;

    const int M = in_sizes[0] / N_EMBD;   // 8192
    constexpr int SMEM_GEMM = 102400;

    cudaFuncSetAttribute(gemm_kernel<true, true>,
                         cudaFuncAttributeMaxDynamicSharedMemorySize, SMEM_GEMM);
    cudaFuncSetAttribute(gemm_kernel<false, false>,
                         cudaFuncAttributeMaxDynamicSharedMemorySize, SMEM_GEMM);

    void* p;
    cudaGetSymbolAddress(&p, g_xq);      signed char* xq      = (signed char*)p;
    cudaGetSymbolAddress(&p, g_wq_fc);   signed char* wq_fc   = (signed char*)p;
    cudaGetSymbolAddress(&p, g_wq_proj); signed char* wq_proj = (signed char*)p;
    cudaGetSymbolAddress(&p, g_h);       float* h     = (float*)p;
    cudaGetSymbolAddress(&p, g_hq);      signed char* hq = (signed char*)p;
    cudaGetSymbolAddress(&p, g_t1);      float* t1    = (float*)p;
    cudaGetSymbolAddress(&p, g_t2);      float* t2    = (float*)p;
    cudaGetSymbolAddress(&p, g_tpart);   float* tpart = (float*)p;
    cudaGetSymbolAddress(&p, g_maxbits); int* mb      = (int*)p;

    init_kernel<<<1, 32>>>(mb);

    absmax_kernel<<<512, 256>>>((const float4*)W_fc,   D_FF * N_EMBD / 4, mb + 1);
    absmax_kernel<<<512, 256>>>((const float4*)W_proj, N_EMBD * D_FF / 4, mb + 2);

    rowdot_x_kernel<<<M / 64, 256>>>(x, A_fc, N_EMBD, t1, mb + 0);

    quant_kernel<<<2048, 256>>>((const float4*)x,      M * N_EMBD / 4,    mb + 0, (char4*)xq);
    quant_kernel<<<1024, 256>>>((const float4*)W_fc,   D_FF * N_EMBD / 4, mb + 1, (char4*)wq_fc);
    quant_kernel<<<1024, 256>>>((const float4*)W_proj, N_EMBD * D_FF / 4, mb + 2, (char4*)wq_proj);

    // GEMM1 + bias + LoRA + GELU -> h; fused partial t2 + max|h|
    gemm_kernel<true, true><<<dim3(D_FF / 128, M / 128), 128, SMEM_GEMM>>>(
        xq, wq_fc, b_fc, t1, B_fc, mb + 0, mb + 1, h,
        A_proj, tpart, mb + 3, M, D_FF, N_EMBD);

    reduce_t2_kernel<<<(M * R + 255) / 256, 256>>>(tpart, t2, M * R, NB2);

    quant_kernel<<<4096, 256>>>((const float4*)h, M * D_FF / 4, mb + 3, (char4*)hq);

    // GEMM2 + bias + LoRA -> out
    gemm_kernel<false, false><<<dim3(N_EMBD / 128, M / 128), 128, SMEM_GEMM>>>(
        hq, wq_proj, b_proj, t2, B_proj, mb + 3, mb + 2, out,
        nullptr, nullptr, nullptr, M, N_EMBD, D_FF);
}

// round 13
// speedup vs baseline: 1.0103x; 1.0103x over previous
#include <cuda_runtime.h>
#include <cuda_bf16.h>
#include <cstdint>

static constexpr int N_EMBD = 1024;
static constexpr int D_FF   = 4096;
static constexpr int MAX_M  = 8192;
static constexpr int R      = 16;
static constexpr int NB2    = D_FF / 128;   // t2 partial slice count (32)

// ---------------- scratch (device globals; no allocations allowed) ----------
__device__ signed char g_xq[(size_t)MAX_M * N_EMBD];
__device__ signed char g_wq_fc[(size_t)D_FF * N_EMBD];
__device__ signed char g_wq_proj[(size_t)N_EMBD * D_FF];
__device__ float       g_h[(size_t)MAX_M * D_FF];
__device__ signed char g_hq[(size_t)MAX_M * D_FF];
__device__ float       g_t1[(size_t)MAX_M * R];
__device__ float       g_t2[(size_t)MAX_M * R];
__device__ float       g_tpart[(size_t)NB2 * MAX_M * R];
__device__ int         g_maxbits[4];

__device__ __forceinline__ void cp_async16(void* d, const void* s) {
    unsigned u = (unsigned)__cvta_generic_to_shared(d);
    asm volatile("cp.async.cg.shared.global [%0], [%1], 16;\n" :: "r"(u), "l"(s));
}
__device__ __forceinline__ void cp_commit() {
    asm volatile("cp.async.commit_group;\n" ::: "memory");
}
__device__ __forceinline__ uint32_t smem_u32(const void* p) {
    return (uint32_t)__cvta_generic_to_shared(p);
}
__device__ __forceinline__ void ldsm4(uint32_t* r, uint32_t addr) {
    asm volatile("ldmatrix.sync.aligned.m8n8.x4.shared.b16 {%0,%1,%2,%3}, [%4];"
        : "=r"(r[0]), "=r"(r[1]), "=r"(r[2]), "=r"(r[3]) : "r"(addr));
}
__device__ __forceinline__ void imma(int* d, const uint32_t* a, const uint32_t* b) {
    asm volatile("mma.sync.aligned.m16n8k32.row.col.s32.s8.s8.s32 "
        "{%0,%1,%2,%3}, {%4,%5,%6,%7}, {%8,%9}, {%0,%1,%2,%3};"
        : "+r"(d[0]), "+r"(d[1]), "+r"(d[2]), "+r"(d[3])
        : "r"(a[0]), "r"(a[1]), "r"(a[2]), "r"(a[3]), "r"(b[0]), "r"(b[1]));
}

// ---------------------------------------------------------------------------
__global__ void init_kernel(int* mb) { if (threadIdx.x < 4) mb[threadIdx.x] = 0; }

__global__ void absmax_kernel(const float4* __restrict__ x, int n4, int* __restrict__ out) {
    float m = 0.f;
    for (int i = blockIdx.x * blockDim.x + threadIdx.x; i < n4; i += gridDim.x * blockDim.x) {
        float4 v = x[i];
        m = fmaxf(m, fmaxf(fmaxf(fabsf(v.x), fabsf(v.y)), fmaxf(fabsf(v.z), fabsf(v.w))));
    }
    #pragma unroll
    for (int o = 16; o; o >>= 1) m = fmaxf(m, __shfl_down_sync(0xffffffffu, m, o));
    __shared__ float sm[8];
    if ((threadIdx.x & 31) == 0) sm[threadIdx.x >> 5] = m;
    __syncthreads();
    if (threadIdx.x == 0) {
        float mm = sm[0];
        #pragma unroll
        for (int w = 1; w < 8; w++) mm = fmaxf(mm, sm[w]);
        atomicMax(out, __float_as_int(mm));
    }
}

// t1 = X @ A^T with fused abs-max (the 32us-measured shape from R6/R10)
__global__ void __launch_bounds__(256) rowdot_x_kernel(
    const float* __restrict__ X, const float* __restrict__ A, int K,
    float* __restrict__ T, int* __restrict__ maxout)
{
    constexpr int LDS = 36;
    constexpr int STG = (64 + 16) * LDS;
    __shared__ __align__(16) float sm[3 * STG];
    __shared__ float mred[8];
    const int tid = threadIdx.x;
    const int m0  = blockIdx.x * 64;
    const int rg  = tid >> 3, cg = tid & 7;
    const float* Xg = X + (size_t)m0 * K;

    auto issue = [&](int kt) {
        float* Xs = sm + (kt % 3) * STG;
        float* As = Xs + 64 * LDS;
        #pragma unroll
        for (int l = 0; l < 2; l++) {
            int i = tid + l * 256, r = i >> 3, c = i & 7;
            cp_async16(Xs + r * LDS + c * 4, Xg + (size_t)r * K + kt * 32 + c * 4);
        }
        if (tid < 128) {
            int r = tid >> 3, c = tid & 7;
            cp_async16(As + r * LDS + c * 4, A + (size_t)r * K + kt * 32 + c * 4);
        }
        cp_commit();
    };

    const int KT = K / 32;
    issue(0); issue(1);
    float acc[2][2] = {};
    float mx = 0.f;

    for (int kt = 0; kt < KT; kt++) {
        asm volatile("cp.async.wait_group 1;\n" ::: "memory");
        __syncthreads();
        if (kt + 2 < KT) issue(kt + 2); else cp_commit();
        const float* Xs = sm + (kt % 3) * STG;
        const float* As = Xs + 64 * LDS;
        #pragma unroll
        for (int kq = 0; kq < 8; kq++) {
            float4 xv0 = *(const float4*)(Xs + (rg * 2)     * LDS + kq * 4);
            float4 xv1 = *(const float4*)(Xs + (rg * 2 + 1) * LDS + kq * 4);
            float4 av0 = *(const float4*)(As + (cg * 2)     * LDS + kq * 4);
            float4 av1 = *(const float4*)(As + (cg * 2 + 1) * LDS + kq * 4);
            mx = fmaxf(mx, fmaxf(fmaxf(fabsf(xv0.x), fabsf(xv0.y)), fmaxf(fabsf(xv0.z), fabsf(xv0.w))));
            mx = fmaxf(mx, fmaxf(fmaxf(fabsf(xv1.x), fabsf(xv1.y)), fmaxf(fabsf(xv1.z), fabsf(xv1.w))));
            acc[0][0] += xv0.x*av0.x + xv0.y*av0.y + xv0.z*av0.z + xv0.w*av0.w;
            acc[0][1] += xv0.x*av1.x + xv0.y*av1.y + xv0.z*av1.z + xv0.w*av1.w;
            acc[1][0] += xv1.x*av0.x + xv1.y*av0.y + xv1.z*av0.z + xv1.w*av0.w;
            acc[1][1] += xv1.x*av1.x + xv1.y*av1.y + xv1.z*av1.z + xv1.w*av1.w;
        }
        __syncthreads();
    }
    #pragma unroll
    for (int ii = 0; ii < 2; ii++)
        #pragma unroll
        for (int jj = 0; jj < 2; jj++)
            T[(size_t)(m0 + rg * 2 + ii) * R + cg * 2 + jj] = acc[ii][jj];

    #pragma unroll
    for (int o = 16; o; o >>= 1) mx = fmaxf(mx, __shfl_down_sync(0xffffffffu, mx, o));
    if ((tid & 31) == 0) mred[tid >> 5] = mx;
    __syncthreads();
    if (tid == 0) {
        float m = mred[0];
        #pragma unroll
        for (int i = 1; i < 8; i++) m = fmaxf(m, mred[i]);
        atomicMax(maxout, __float_as_int(m));
    }
}

// q = clip(round(v/scale), -127, 127), stored as int8
__global__ void quant_kernel(const float4* __restrict__ src, int n4,
                             const int* __restrict__ mb, char4* __restrict__ dst) {
    const float s = fmaxf(__int_as_float(*mb), 1e-8f) / 127.0f;
    for (int i = blockIdx.x * blockDim.x + threadIdx.x; i < n4; i += gridDim.x * blockDim.x) {
        float4 v = src[i];
        char4 q;
        q.x = (signed char)(int)fminf(fmaxf(rintf(v.x / s), -127.f), 127.f);
        q.y = (signed char)(int)fminf(fmaxf(rintf(v.y / s), -127.f), 127.f);
        q.z = (signed char)(int)fminf(fmaxf(rintf(v.z / s), -127.f), 127.f);
        q.w = (signed char)(int)fminf(fmaxf(rintf(v.w / s), -127.f), 127.f);
        dst[i] = q;
    }
}

// fixed-order reduction of t2 partial slices (deterministic)
__global__ void reduce_t2_kernel(const float* __restrict__ Tpart, float* __restrict__ T2,
                                 int n, int nb) {
    int i = blockIdx.x * blockDim.x + threadIdx.x;
    if (i < n) {
        float s = 0.f;
        for (int b = 0; b < nb; b++) s += Tpart[(size_t)b * n + i];
        T2[i] = s;
    }
}

// ---------------------------------------------------------------------------
// int8 GEMM with fused epilogue. BM=128 BN=128 BK=64. 8 warps (2m x 4n),
// warp tile 64x32 (best-measured mainloop, 514us run). 4-stage cp.async,
// wait_group 2; the issue(kt+3) prefetch runs BEFORE the compute block —
// stage (kt+3)&3 == (kt-1)&3 is protected by the top-of-iteration barrier,
// so the refill is race-free and overlaps the LDSM/IMMA work.
// ---------------------------------------------------------------------------
template <bool GELU, bool FUSE_T2>
__global__ void __launch_bounds__(256, 2) gemm_kernel(
    const signed char* __restrict__ Aq, const signed char* __restrict__ Bq,
    const float* __restrict__ bias, const float* __restrict__ T,
    const float* __restrict__ Blora, const int* __restrict__ mbA,
    const int* __restrict__ mbW, float* __restrict__ C,
    const float* __restrict__ Ap, float* __restrict__ Tpart, int* __restrict__ hmax,
    int M, int N, int K)
{
    constexpr int BM = 128, BN = 128, BK = 64, LDA = 80;
    constexpr int STAGE = 2 * BM * LDA;
    extern __shared__ __align__(16) char smem[];  // 4 * 20480 = 81920 bytes
    __shared__ float hred[8];

    const int tid = threadIdx.x;
    const int lane = tid & 31;
    const int m0 = blockIdx.y * BM, n0 = blockIdx.x * BN;
    const int w = tid >> 5, wm = w & 1, wn = w >> 1;

    const signed char* Agb = Aq + (size_t)m0 * K;
    const signed char* Bgb = Bq + (size_t)n0 * K;

    auto issue = [&](int kt) {
        char* as = smem + (kt & 3) * STAGE;
        char* bs = as + BM * LDA;
        const signed char* ag = Agb + kt * BK;
        const signed char* bg = Bgb + kt * BK;
        #pragma unroll
        for (int l = 0; l < 2; l++) {
            int i = tid + l * 256, r = i >> 2, c = i & 3;
            cp_async16(as + r * LDA + c * 16, ag + (size_t)r * K + c * 16);
        }
        #pragma unroll
        for (int l = 0; l < 2; l++) {
            int i = tid + l * 256, r = i >> 2, c = i & 3;
            cp_async16(bs + r * LDA + c * 16, bg + (size_t)r * K + c * 16);
        }
        cp_commit();
    };

    const uint32_t a_off = (uint32_t)((wm * 64 + (lane & 15)) * LDA + ((lane >> 4) << 4));
    const int brow = (lane & 7) + ((lane & 16) >> 1);
    const uint32_t b_off = (uint32_t)((wn * 32 + brow) * LDA + (((lane >> 3) & 1) << 4));

    const int KT = K / BK;
    issue(0); issue(1); issue(2);

    int d[4][4][4];
    #pragma unroll
    for (int i = 0; i < 4; i++)
        #pragma unroll
        for (int j = 0; j < 4; j++)
            #pragma unroll
            for (int q = 0; q < 4; q++) d[i][j][q] = 0;

    for (int kt = 0; kt < KT; kt++) {
        asm volatile("cp.async.wait_group 2;\n" ::: "memory");
        __syncthreads();
        if (kt + 3 < KT) issue(kt + 3); else cp_commit();

        uint32_t a_s = smem_u32(smem + (kt & 3) * STAGE);
        uint32_t b_s = a_s + BM * LDA;
        #pragma unroll
        for (int ks = 0; ks < 2; ks++) {
            uint32_t af[4][4], bf[4][2];
            #pragma unroll
            for (int i = 0; i < 4; i++)
                ldsm4(af[i], a_s + a_off + i * (16 * LDA) + ks * 32);
            {
                uint32_t t[4];
                ldsm4(t, b_s + b_off + ks * 32);
                bf[0][0] = t[0]; bf[0][1] = t[1]; bf[1][0] = t[2]; bf[1][1] = t[3];
                ldsm4(t, b_s + b_off + 16 * LDA + ks * 32);
                bf[2][0] = t[0]; bf[2][1] = t[1]; bf[3][0] = t[2]; bf[3][1] = t[3];
            }
            #pragma unroll
            for (int i = 0; i < 4; i++)
                #pragma unroll
                for (int j = 0; j < 4; j++)
                    imma(d[i][j], af[i], bf[j]);
        }
    }
    asm volatile("cp.async.wait_group 0;\n" ::: "memory");
    __syncthreads();

    // ---------------- epilogue (reuses pipeline smem) ----------------
    const float sA = fmaxf(__int_as_float(*mbA), 1e-8f) / 127.0f;
    const float sW = fmaxf(__int_as_float(*mbW), 1e-8f) / 127.0f;
    const float sc = sA * sW;

    int*   parkI = (int*)smem;
    float* parkF = (float*)smem;
    float* Tsm   = (float*)(smem + 34816);
    float* Bl    = (float*)(smem + 43008);
    float* Apsm  = (float*)(smem + 51200);

    #pragma unroll
    for (int l = 0; l < 2; l++) {
        ((float4*)Bl)[tid + l * 256]  = ((const float4*)(Blora + (size_t)n0 * R))[tid + l * 256];
        ((float4*)Tsm)[tid + l * 256] = ((const float4*)(T + (size_t)m0 * R))[tid + l * 256];
    }
    if (FUSE_T2)
        for (int i = tid; i < R * BN; i += 256) {
            int j = i >> 7, c = i & 127;
            Apsm[j * 132 + c] = Ap[(size_t)j * N + n0 + c];
        }

    float hm = 0.f;
    float acc2[8] = {};
    const int jj = tid & 15, rgp = tid >> 4;
    const int ec = tid & 63, er0 = tid >> 6;

    #pragma unroll
    for (int half = 0; half < 2; half++) {
        __syncthreads();
        if ((wn >> 1) == half) {
            #pragma unroll
            for (int i = 0; i < 4; i++) {
                int r0 = wm * 64 + i * 16 + (lane >> 2);
                #pragma unroll
                for (int j = 0; j < 4; j++) {
                    int c = (wn & 1) * 32 + j * 8 + (lane & 3) * 2;
                    parkI[r0 * 68 + c]           = d[i][j][0];
                    parkI[r0 * 68 + c + 1]       = d[i][j][1];
                    parkI[(r0 + 8) * 68 + c]     = d[i][j][2];
                    parkI[(r0 + 8) * 68 + c + 1] = d[i][j][3];
                }
            }
        }
        __syncthreads();

        const int gc = half * 64 + ec;
        const float bsv = __ldg(bias + n0 + gc);
        float4 bl0 = *(float4*)(Bl + gc * 16);
        float4 bl1 = *(float4*)(Bl + gc * 16 + 4);
        float4 bl2 = *(float4*)(Bl + gc * 16 + 8);
        float4 bl3 = *(float4*)(Bl + gc * 16 + 12);

        for (int r = er0; r < BM; r += 4) {
            float4 t0 = *(float4*)(Tsm + r * 16);
            float4 t1 = *(float4*)(Tsm + r * 16 + 4);
            float4 t2v = *(float4*)(Tsm + r * 16 + 8);
            float4 t3 = *(float4*)(Tsm + r * 16 + 12);
            float lor = t0.x*bl0.x + t0.y*bl0.y + t0.z*bl0.z + t0.w*bl0.w
                      + t1.x*bl1.x + t1.y*bl1.y + t1.z*bl1.z + t1.w*bl1.w
                      + t2v.x*bl2.x + t2v.y*bl2.y + t2v.z*bl2.z + t2v.w*bl2.w
                      + t3.x*bl3.x + t3.y*bl3.y + t3.z*bl3.z + t3.w*bl3.w;
            float v = sc * (float)parkI[r * 68 + ec] + bsv + 2.0f * lor;
            if (GELU) v = 0.5f * v * (1.0f + erff(v * 0.7071067811865476f));
            C[(size_t)(m0 + r) * N + n0 + gc] = v;
            if (FUSE_T2) { parkF[r * 68 + ec] = v; hm = fmaxf(hm, fabsf(v)); }
        }
        if (FUSE_T2) {
            __syncthreads();
            #pragma unroll
            for (int cq = 0; cq < 16; cq++) {
                float4 av = *(float4*)(Apsm + jj * 132 + half * 64 + cq * 4);
                #pragma unroll
                for (int ii = 0; ii < 8; ii++) {
                    float4 hv = *(float4*)(parkF + (rgp * 8 + ii) * 68 + cq * 4);
                    acc2[ii] += hv.x * av.x + hv.y * av.y + hv.z * av.z + hv.w * av.w;
                }
            }
        }
    }
    if (FUSE_T2) {
        #pragma unroll
        for (int ii = 0; ii < 8; ii++)
            Tpart[(size_t)blockIdx.x * ((size_t)M * R)
                  + (size_t)(m0 + rgp * 8 + ii) * R + jj] = acc2[ii];
        #pragma unroll
        for (int o = 16; o; o >>= 1) hm = fmaxf(hm, __shfl_down_sync(0xffffffffu, hm, o));
        if ((tid & 31) == 0) hred[w] = hm;
        __syncthreads();
        if (tid == 0) {
            float m = hred[0];
            #pragma unroll
            for (int i = 1; i < 8; i++) m = fmaxf(m, hred[i]);
            atomicMax(hmax, __float_as_int(m));
        }
    }
}

// ---------------------------------------------------------------------------
extern "C" void kernel_launch(void* const* d_in, const int* in_sizes, int n_in,
                              void* d_out, int out_size) {
    const float* x      = (const float*)d_in[0];
    const float* W_fc   = (const float*)d_in[1];
    const float* b_fc   = (const float*)d_in[2];
    const float* A_fc   = (const float*)d_in[3];
    const float* B_fc   = (const float*)d_in[4];
    const float* W_proj = (const float*)d_in[5];
    const float* b_proj = (const float*)d_in[6];
    const float* A_proj = (const float*)d_in[7];
    const float* B_proj = (const float*)d_in[8];
    float* out = (float*)d_out;

    const int M = in_sizes[0] / N_EMBD;   // 8192
    constexpr int SMEM_GEMM = 81920;

    cudaFuncSetAttribute(gemm_kernel<true, true>,
                         cudaFuncAttributeMaxDynamicSharedMemorySize, SMEM_GEMM);
    cudaFuncSetAttribute(gemm_kernel<false, false>,
                         cudaFuncAttributeMaxDynamicSharedMemorySize, SMEM_GEMM);

    void* p;
    cudaGetSymbolAddress(&p, g_xq);      signed char* xq      = (signed char*)p;
    cudaGetSymbolAddress(&p, g_wq_fc);   signed char* wq_fc   = (signed char*)p;
    cudaGetSymbolAddress(&p, g_wq_proj); signed char* wq_proj = (signed char*)p;
    cudaGetSymbolAddress(&p, g_h);       float* h     = (float*)p;
    cudaGetSymbolAddress(&p, g_hq);      signed char* hq = (signed char*)p;
    cudaGetSymbolAddress(&p, g_t1);      float* t1    = (float*)p;
    cudaGetSymbolAddress(&p, g_t2);      float* t2    = (float*)p;
    cudaGetSymbolAddress(&p, g_tpart);   float* tpart = (float*)p;
    cudaGetSymbolAddress(&p, g_maxbits); int* mb      = (int*)p;

    init_kernel<<<1, 32>>>(mb);

    absmax_kernel<<<512, 256>>>((const float4*)W_fc,   D_FF * N_EMBD / 4, mb + 1);
    absmax_kernel<<<512, 256>>>((const float4*)W_proj, N_EMBD * D_FF / 4, mb + 2);

    rowdot_x_kernel<<<M / 64, 256>>>(x, A_fc, N_EMBD, t1, mb + 0);

    quant_kernel<<<2048, 256>>>((const float4*)x,      M * N_EMBD / 4,    mb + 0, (char4*)xq);
    quant_kernel<<<1024, 256>>>((const float4*)W_fc,   D_FF * N_EMBD / 4, mb + 1, (char4*)wq_fc);
    quant_kernel<<<1024, 256>>>((const float4*)W_proj, N_EMBD * D_FF / 4, mb + 2, (char4*)wq_proj);

    // GEMM1 + bias + LoRA + GELU -> h; fused t2 partials + abs-max of h
    gemm_kernel<true, true><<<dim3(D_FF / 128, M / 128), 256, SMEM_GEMM>>>(
        xq, wq_fc, b_fc, t1, B_fc, mb + 0, mb + 1, h,
        A_proj, tpart, mb + 3, M, D_FF, N_EMBD);

    reduce_t2_kernel<<<(M * R + 255) / 256, 256>>>(tpart, t2, M * R, NB2);

    quant_kernel<<<4096, 256>>>((const float4*)h, M * D_FF / 4, mb + 3, (char4*)hq);

    // GEMM2 + bias + LoRA -> out
    gemm_kernel<false, false><<<dim3(N_EMBD / 128, M / 128), 256, SMEM_GEMM>>>(
        hq, wq_proj, b_proj, t2, B_proj, mb + 3, mb + 2, out,
        nullptr, nullptr, nullptr, M, N_EMBD, D_FF);
}

// round 14
// speedup vs baseline: 1.0610x; 1.0502x over previous
#include <cuda_runtime.h>
#include <cuda_bf16.h>
#include <cstdint>

static constexpr int N_EMBD = 1024;
static constexpr int D_FF   = 4096;
static constexpr int MAX_M  = 8192;
static constexpr int R      = 16;
static constexpr int NB2    = D_FF / 128;   // t2 partial slice count (32)

// ---------------- scratch (device globals; no allocations allowed) ----------
__device__ signed char g_xq[(size_t)MAX_M * N_EMBD];
__device__ signed char g_wq_fc[(size_t)D_FF * N_EMBD];
__device__ signed char g_wq_proj[(size_t)N_EMBD * D_FF];
__device__ float       g_h[(size_t)MAX_M * D_FF];
__device__ signed char g_hq[(size_t)MAX_M * D_FF];
__device__ float       g_t1[(size_t)MAX_M * R];
__device__ float       g_t2[(size_t)MAX_M * R];
__device__ float       g_tpart[(size_t)NB2 * MAX_M * R];
__device__ int         g_maxbits[4];

__device__ __forceinline__ void cp_async16(void* d, const void* s) {
    unsigned u = (unsigned)__cvta_generic_to_shared(d);
    asm volatile("cp.async.cg.shared.global [%0], [%1], 16;\n" :: "r"(u), "l"(s));
}
__device__ __forceinline__ void cp_commit() {
    asm volatile("cp.async.commit_group;\n" ::: "memory");
}
__device__ __forceinline__ uint32_t smem_u32(const void* p) {
    return (uint32_t)__cvta_generic_to_shared(p);
}
__device__ __forceinline__ void ldsm4(uint32_t* r, uint32_t addr) {
    asm volatile("ldmatrix.sync.aligned.m8n8.x4.shared.b16 {%0,%1,%2,%3}, [%4];"
        : "=r"(r[0]), "=r"(r[1]), "=r"(r[2]), "=r"(r[3]) : "r"(addr));
}
__device__ __forceinline__ void imma(int* d, const uint32_t* a, const uint32_t* b) {
    asm volatile("mma.sync.aligned.m16n8k32.row.col.s32.s8.s8.s32 "
        "{%0,%1,%2,%3}, {%4,%5,%6,%7}, {%8,%9}, {%0,%1,%2,%3};"
        : "+r"(d[0]), "+r"(d[1]), "+r"(d[2]), "+r"(d[3])
        : "r"(a[0]), "r"(a[1]), "r"(a[2]), "r"(a[3]), "r"(b[0]), "r"(b[1]));
}

// ---------------------------------------------------------------------------
__global__ void init_kernel(int* mb) { if (threadIdx.x < 4) mb[threadIdx.x] = 0; }

__global__ void absmax_kernel(const float4* __restrict__ x, int n4, int* __restrict__ out) {
    float m = 0.f;
    for (int i = blockIdx.x * blockDim.x + threadIdx.x; i < n4; i += gridDim.x * blockDim.x) {
        float4 v = x[i];
        m = fmaxf(m, fmaxf(fmaxf(fabsf(v.x), fabsf(v.y)), fmaxf(fabsf(v.z), fabsf(v.w))));
    }
    #pragma unroll
    for (int o = 16; o; o >>= 1) m = fmaxf(m, __shfl_down_sync(0xffffffffu, m, o));
    __shared__ float sm[8];
    if ((threadIdx.x & 31) == 0) sm[threadIdx.x >> 5] = m;
    __syncthreads();
    if (threadIdx.x == 0) {
        float mm = sm[0];
        #pragma unroll
        for (int w = 1; w < 8; w++) mm = fmaxf(mm, sm[w]);
        atomicMax(out, __float_as_int(mm));
    }
}

// t1 = X @ A^T with fused abs-max (the 32us-measured shape)
__global__ void __launch_bounds__(256) rowdot_x_kernel(
    const float* __restrict__ X, const float* __restrict__ A, int K,
    float* __restrict__ T, int* __restrict__ maxout)
{
    constexpr int LDS = 36;
    constexpr int STG = (64 + 16) * LDS;
    __shared__ __align__(16) float sm[3 * STG];
    __shared__ float mred[8];
    const int tid = threadIdx.x;
    const int m0  = blockIdx.x * 64;
    const int rg  = tid >> 3, cg = tid & 7;
    const float* Xg = X + (size_t)m0 * K;

    auto issue = [&](int kt) {
        float* Xs = sm + (kt % 3) * STG;
        float* As = Xs + 64 * LDS;
        #pragma unroll
        for (int l = 0; l < 2; l++) {
            int i = tid + l * 256, r = i >> 3, c = i & 7;
            cp_async16(Xs + r * LDS + c * 4, Xg + (size_t)r * K + kt * 32 + c * 4);
        }
        if (tid < 128) {
            int r = tid >> 3, c = tid & 7;
            cp_async16(As + r * LDS + c * 4, A + (size_t)r * K + kt * 32 + c * 4);
        }
        cp_commit();
    };

    const int KT = K / 32;
    issue(0); issue(1);
    float acc[2][2] = {};
    float mx = 0.f;

    for (int kt = 0; kt < KT; kt++) {
        asm volatile("cp.async.wait_group 1;\n" ::: "memory");
        __syncthreads();
        if (kt + 2 < KT) issue(kt + 2); else cp_commit();
        const float* Xs = sm + (kt % 3) * STG;
        const float* As = Xs + 64 * LDS;
        #pragma unroll
        for (int kq = 0; kq < 8; kq++) {
            float4 xv0 = *(const float4*)(Xs + (rg * 2)     * LDS + kq * 4);
            float4 xv1 = *(const float4*)(Xs + (rg * 2 + 1) * LDS + kq * 4);
            float4 av0 = *(const float4*)(As + (cg * 2)     * LDS + kq * 4);
            float4 av1 = *(const float4*)(As + (cg * 2 + 1) * LDS + kq * 4);
            mx = fmaxf(mx, fmaxf(fmaxf(fabsf(xv0.x), fabsf(xv0.y)), fmaxf(fabsf(xv0.z), fabsf(xv0.w))));
            mx = fmaxf(mx, fmaxf(fmaxf(fabsf(xv1.x), fabsf(xv1.y)), fmaxf(fabsf(xv1.z), fabsf(xv1.w))));
            acc[0][0] += xv0.x*av0.x + xv0.y*av0.y + xv0.z*av0.z + xv0.w*av0.w;
            acc[0][1] += xv0.x*av1.x + xv0.y*av1.y + xv0.z*av1.z + xv0.w*av1.w;
            acc[1][0] += xv1.x*av0.x + xv1.y*av0.y + xv1.z*av0.z + xv1.w*av0.w;
            acc[1][1] += xv1.x*av1.x + xv1.y*av1.y + xv1.z*av1.z + xv1.w*av1.w;
        }
        __syncthreads();
    }
    #pragma unroll
    for (int ii = 0; ii < 2; ii++)
        #pragma unroll
        for (int jj = 0; jj < 2; jj++)
            T[(size_t)(m0 + rg * 2 + ii) * R + cg * 2 + jj] = acc[ii][jj];

    #pragma unroll
    for (int o = 16; o; o >>= 1) mx = fmaxf(mx, __shfl_down_sync(0xffffffffu, mx, o));
    if ((tid & 31) == 0) mred[tid >> 5] = mx;
    __syncthreads();
    if (tid == 0) {
        float m = mred[0];
        #pragma unroll
        for (int i = 1; i < 8; i++) m = fmaxf(m, mred[i]);
        atomicMax(maxout, __float_as_int(m));
    }
}

// q = clip(round(v/scale), -127, 127), stored as int8
__global__ void quant_kernel(const float4* __restrict__ src, int n4,
                             const int* __restrict__ mb, char4* __restrict__ dst) {
    const float s = fmaxf(__int_as_float(*mb), 1e-8f) / 127.0f;
    for (int i = blockIdx.x * blockDim.x + threadIdx.x; i < n4; i += gridDim.x * blockDim.x) {
        float4 v = src[i];
        char4 q;
        q.x = (signed char)(int)fminf(fmaxf(rintf(v.x / s), -127.f), 127.f);
        q.y = (signed char)(int)fminf(fmaxf(rintf(v.y / s), -127.f), 127.f);
        q.z = (signed char)(int)fminf(fmaxf(rintf(v.z / s), -127.f), 127.f);
        q.w = (signed char)(int)fminf(fmaxf(rintf(v.w / s), -127.f), 127.f);
        dst[i] = q;
    }
}

// fixed-order reduction of t2 partial slices (deterministic)
__global__ void reduce_t2_kernel(const float* __restrict__ Tpart, float* __restrict__ T2,
                                 int n, int nb) {
    int i = blockIdx.x * blockDim.x + threadIdx.x;
    if (i < n) {
        float s = 0.f;
        for (int b = 0; b < nb; b++) s += Tpart[(size_t)b * n + i];
        T2[i] = s;
    }
}

// ---------------------------------------------------------------------------
// int8 GEMM with fused epilogue. BM=128 BN=128 BK=64. 8 warps (2m x 4n),
// warp tile 64x32, 4-stage cp.async, wait_group 2 — the exact 514us-measured
// mainloop: compute FIRST, then issue(kt+3) (early issue measured 20us slower).
// ---------------------------------------------------------------------------
template <bool GELU, bool FUSE_T2>
__global__ void __launch_bounds__(256, 2) gemm_kernel(
    const signed char* __restrict__ Aq, const signed char* __restrict__ Bq,
    const float* __restrict__ bias, const float* __restrict__ T,
    const float* __restrict__ Blora, const int* __restrict__ mbA,
    const int* __restrict__ mbW, float* __restrict__ C,
    const float* __restrict__ Ap, float* __restrict__ Tpart, int* __restrict__ hmax,
    int M, int N, int K)
{
    constexpr int BM = 128, BN = 128, BK = 64, LDA = 80;
    constexpr int STAGE = 2 * BM * LDA;
    extern __shared__ __align__(16) char smem[];  // 4 * 20480 = 81920 bytes
    __shared__ float hred[8];

    const int tid = threadIdx.x;
    const int lane = tid & 31;
    const int m0 = blockIdx.y * BM, n0 = blockIdx.x * BN;
    const int w = tid >> 5, wm = w & 1, wn = w >> 1;

    const signed char* Agb = Aq + (size_t)m0 * K;
    const signed char* Bgb = Bq + (size_t)n0 * K;

    auto issue = [&](int kt) {
        char* as = smem + (kt & 3) * STAGE;
        char* bs = as + BM * LDA;
        const signed char* ag = Agb + kt * BK;
        const signed char* bg = Bgb + kt * BK;
        #pragma unroll
        for (int l = 0; l < 2; l++) {
            int i = tid + l * 256, r = i >> 2, c = i & 3;
            cp_async16(as + r * LDA + c * 16, ag + (size_t)r * K + c * 16);
        }
        #pragma unroll
        for (int l = 0; l < 2; l++) {
            int i = tid + l * 256, r = i >> 2, c = i & 3;
            cp_async16(bs + r * LDA + c * 16, bg + (size_t)r * K + c * 16);
        }
        cp_commit();
    };

    const uint32_t a_off = (uint32_t)((wm * 64 + (lane & 15)) * LDA + ((lane >> 4) << 4));
    const int brow = (lane & 7) + ((lane & 16) >> 1);
    const uint32_t b_off = (uint32_t)((wn * 32 + brow) * LDA + (((lane >> 3) & 1) << 4));

    const int KT = K / BK;
    issue(0); issue(1); issue(2);

    int d[4][4][4];
    #pragma unroll
    for (int i = 0; i < 4; i++)
        #pragma unroll
        for (int j = 0; j < 4; j++)
            #pragma unroll
            for (int q = 0; q < 4; q++) d[i][j][q] = 0;

    for (int kt = 0; kt < KT; kt++) {
        asm volatile("cp.async.wait_group 2;\n" ::: "memory");
        __syncthreads();

        uint32_t a_s = smem_u32(smem + (kt & 3) * STAGE);
        uint32_t b_s = a_s + BM * LDA;
        #pragma unroll
        for (int ks = 0; ks < 2; ks++) {
            uint32_t af[4][4], bf[4][2];
            #pragma unroll
            for (int i = 0; i < 4; i++)
                ldsm4(af[i], a_s + a_off + i * (16 * LDA) + ks * 32);
            {
                uint32_t t[4];
                ldsm4(t, b_s + b_off + ks * 32);
                bf[0][0] = t[0]; bf[0][1] = t[1]; bf[1][0] = t[2]; bf[1][1] = t[3];
                ldsm4(t, b_s + b_off + 16 * LDA + ks * 32);
                bf[2][0] = t[0]; bf[2][1] = t[1]; bf[3][0] = t[2]; bf[3][1] = t[3];
            }
            #pragma unroll
            for (int i = 0; i < 4; i++)
                #pragma unroll
                for (int j = 0; j < 4; j++)
                    imma(d[i][j], af[i], bf[j]);
        }
        if (kt + 3 < KT) issue(kt + 3); else cp_commit();
    }
    asm volatile("cp.async.wait_group 0;\n" ::: "memory");
    __syncthreads();

    // ---------------- epilogue (reuses pipeline smem) ----------------
    const float sA = fmaxf(__int_as_float(*mbA), 1e-8f) / 127.0f;
    const float sW = fmaxf(__int_as_float(*mbW), 1e-8f) / 127.0f;
    const float sc = sA * sW;

    int*   parkI = (int*)smem;
    float* parkF = (float*)smem;
    float* Tsm   = (float*)(smem + 34816);
    float* Bl    = (float*)(smem + 43008);
    float* Apsm  = (float*)(smem + 51200);

    #pragma unroll
    for (int l = 0; l < 2; l++) {
        ((float4*)Bl)[tid + l * 256]  = ((const float4*)(Blora + (size_t)n0 * R))[tid + l * 256];
        ((float4*)Tsm)[tid + l * 256] = ((const float4*)(T + (size_t)m0 * R))[tid + l * 256];
    }
    if (FUSE_T2)
        for (int i = tid; i < R * BN; i += 256) {
            int j = i >> 7, c = i & 127;
            Apsm[j * 132 + c] = Ap[(size_t)j * N + n0 + c];
        }

    float hm = 0.f;
    float acc2[8] = {};
    const int jj = tid & 15, rgp = tid >> 4;
    const int ec = tid & 63, er0 = tid >> 6;

    #pragma unroll
    for (int half = 0; half < 2; half++) {
        __syncthreads();
        if ((wn >> 1) == half) {
            #pragma unroll
            for (int i = 0; i < 4; i++) {
                int r0 = wm * 64 + i * 16 + (lane >> 2);
                #pragma unroll
                for (int j = 0; j < 4; j++) {
                    int c = (wn & 1) * 32 + j * 8 + (lane & 3) * 2;
                    parkI[r0 * 68 + c]           = d[i][j][0];
                    parkI[r0 * 68 + c + 1]       = d[i][j][1];
                    parkI[(r0 + 8) * 68 + c]     = d[i][j][2];
                    parkI[(r0 + 8) * 68 + c + 1] = d[i][j][3];
                }
            }
        }
        __syncthreads();

        const int gc = half * 64 + ec;
        const float bsv = __ldg(bias + n0 + gc);
        float4 bl0 = *(float4*)(Bl + gc * 16);
        float4 bl1 = *(float4*)(Bl + gc * 16 + 4);
        float4 bl2 = *(float4*)(Bl + gc * 16 + 8);
        float4 bl3 = *(float4*)(Bl + gc * 16 + 12);

        for (int r = er0; r < BM; r += 4) {
            float4 t0 = *(float4*)(Tsm + r * 16);
            float4 t1 = *(float4*)(Tsm + r * 16 + 4);
            float4 t2v = *(float4*)(Tsm + r * 16 + 8);
            float4 t3 = *(float4*)(Tsm + r * 16 + 12);
            float lor = t0.x*bl0.x + t0.y*bl0.y + t0.z*bl0.z + t0.w*bl0.w
                      + t1.x*bl1.x + t1.y*bl1.y + t1.z*bl1.z + t1.w*bl1.w
                      + t2v.x*bl2.x + t2v.y*bl2.y + t2v.z*bl2.z + t2v.w*bl2.w
                      + t3.x*bl3.x + t3.y*bl3.y + t3.z*bl3.z + t3.w*bl3.w;
            float v = sc * (float)parkI[r * 68 + ec] + bsv + 2.0f * lor;
            if (GELU) v = 0.5f * v * (1.0f + erff(v * 0.7071067811865476f));
            C[(size_t)(m0 + r) * N + n0 + gc] = v;
            if (FUSE_T2) { parkF[r * 68 + ec] = v; hm = fmaxf(hm, fabsf(v)); }
        }
        if (FUSE_T2) {
            __syncthreads();
            #pragma unroll
            for (int cq = 0; cq < 16; cq++) {
                float4 av = *(float4*)(Apsm + jj * 132 + half * 64 + cq * 4);
                #pragma unroll
                for (int ii = 0; ii < 8; ii++) {
                    float4 hv = *(float4*)(parkF + (rgp * 8 + ii) * 68 + cq * 4);
                    acc2[ii] += hv.x * av.x + hv.y * av.y + hv.z * av.z + hv.w * av.w;
                }
            }
        }
    }
    if (FUSE_T2) {
        #pragma unroll
        for (int ii = 0; ii < 8; ii++)
            Tpart[(size_t)blockIdx.x * ((size_t)M * R)
                  + (size_t)(m0 + rgp * 8 + ii) * R + jj] = acc2[ii];
        #pragma unroll
        for (int o = 16; o; o >>= 1) hm = fmaxf(hm, __shfl_down_sync(0xffffffffu, hm, o));
        if ((tid & 31) == 0) hred[w] = hm;
        __syncthreads();
        if (tid == 0) {
            float m = hred[0];
            #pragma unroll
            for (int i = 1; i < 8; i++) m = fmaxf(m, hred[i]);
            atomicMax(hmax, __float_as_int(m));
        }
    }
}

// ---------------------------------------------------------------------------
extern "C" void kernel_launch(void* const* d_in, const int* in_sizes, int n_in,
                              void* d_out, int out_size) {
    const float* x      = (const float*)d_in[0];
    const float* W_fc   = (const float*)d_in[1];
    const float* b_fc   = (const float*)d_in[2];
    const float* A_fc   = (const float*)d_in[3];
    const float* B_fc   = (const float*)d_in[4];
    const float* W_proj = (const float*)d_in[5];
    const float* b_proj = (const float*)d_in[6];
    const float* A_proj = (const float*)d_in[7];
    const float* B_proj = (const float*)d_in[8];
    float* out = (float*)d_out;

    const int M = in_sizes[0] / N_EMBD;   // 8192
    constexpr int SMEM_GEMM = 81920;

    cudaFuncSetAttribute(gemm_kernel<true, true>,
                         cudaFuncAttributeMaxDynamicSharedMemorySize, SMEM_GEMM);
    cudaFuncSetAttribute(gemm_kernel<false, false>,
                         cudaFuncAttributeMaxDynamicSharedMemorySize, SMEM_GEMM);

    void* p;
    cudaGetSymbolAddress(&p, g_xq);      signed char* xq      = (signed char*)p;
    cudaGetSymbolAddress(&p, g_wq_fc);   signed char* wq_fc   = (signed char*)p;
    cudaGetSymbolAddress(&p, g_wq_proj); signed char* wq_proj = (signed char*)p;
    cudaGetSymbolAddress(&p, g_h);       float* h     = (float*)p;
    cudaGetSymbolAddress(&p, g_hq);      signed char* hq = (signed char*)p;
    cudaGetSymbolAddress(&p, g_t1);      float* t1    = (float*)p;
    cudaGetSymbolAddress(&p, g_t2);      float* t2    = (float*)p;
    cudaGetSymbolAddress(&p, g_tpart);   float* tpart = (float*)p;
    cudaGetSymbolAddress(&p, g_maxbits); int* mb      = (int*)p;

    init_kernel<<<1, 32>>>(mb);

    absmax_kernel<<<512, 256>>>((const float4*)W_fc,   D_FF * N_EMBD / 4, mb + 1);
    absmax_kernel<<<512, 256>>>((const float4*)W_proj, N_EMBD * D_FF / 4, mb + 2);

    rowdot_x_kernel<<<M / 64, 256>>>(x, A_fc, N_EMBD, t1, mb + 0);

    quant_kernel<<<2048, 256>>>((const float4*)x,      M * N_EMBD / 4,    mb + 0, (char4*)xq);
    quant_kernel<<<1024, 256>>>((const float4*)W_fc,   D_FF * N_EMBD / 4, mb + 1, (char4*)wq_fc);
    quant_kernel<<<1024, 256>>>((const float4*)W_proj, N_EMBD * D_FF / 4, mb + 2, (char4*)wq_proj);

    // GEMM1 + bias + LoRA + GELU -> h; fused t2 partials + abs-max of h
    gemm_kernel<true, true><<<dim3(D_FF / 128, M / 128), 256, SMEM_GEMM>>>(
        xq, wq_fc, b_fc, t1, B_fc, mb + 0, mb + 1, h,
        A_proj, tpart, mb + 3, M, D_FF, N_EMBD);

    reduce_t2_kernel<<<(M * R + 255) / 256, 256>>>(tpart, t2, M * R, NB2);

    quant_kernel<<<4096, 256>>>((const float4*)h, M * D_FF / 4, mb + 3, (char4*)hq);

    // GEMM2 + bias + LoRA -> out
    gemm_kernel<false, false><<<dim3(N_EMBD / 128, M / 128), 256, SMEM_GEMM>>>(
        hq, wq_proj, b_proj, t2, B_proj, mb + 3, mb + 2, out,
        nullptr, nullptr, nullptr, M, N_EMBD, D_FF);
}